// round 15
// baseline (speedup 1.0000x reference)
#include <cuda_runtime.h>
#include <cstdint>
#include <cstddef>

// Problem constants
#define HID    512
#define NOBJC  151
#define NRELC  51
#define POOL   4096
#define NREL   65536

// ---------------- k1 (edge_rep) constants ----------------
#define ASTR 36
#define BSTR 136
#define K1_SMEM ((2*128*ASTR + 2*32*BSTR) * 4)

// ---------------- k2 constants ----------------
// BM=128, BN=128, BK=32, 3-stage cp.async, 256 threads (8 warps, 2x4),
// warp tile 64x32, ldmatrix fragment loads. 2 CTAs/SM.
// A stage: [128 m][32 k] stride 36; B stage: [128 n][32 k] stride 36.
#define BSTR2 36
#define ABUF (128*ASTR*4)          // 18432 B
#define BBUF (128*BSTR2*4)         // 18432 B
#define STG  (ABUF + BBUF)         // 36864
#define VSTR 132
#define WSTR 72
// V/W union the stage region (time-disjoint):
#define OFFV 0
#define OFFW (128*VSTR*4)          // 67584 ; V+W = 104448 <= 3*STG = 110592
#define OFFI (3*STG)               // 110592
#define K2S  (OFFI + 2*128*4)      // 111616

// Prepared (pre-rounded tf32) buffers
__device__ float g_edge_rep[(size_t)8192 * 1024];   // tf32-rounded, [row][k]
__device__ float g_wpcT[(size_t)4096 * 1024];       // tf32-rounded W_post_cat, TRANSPOSED [n][k]
__device__ float g_wctxT[(size_t)256 * 1024];       // tf32-rounded W_ctx, zero-padded, TRANSPOSED [n][k]

// ---------------------------------------------------------------------------
__device__ __forceinline__ unsigned f2tf(float f) {
    unsigned u;
    asm("cvt.rna.tf32.f32 %0, %1;" : "=r"(u) : "f"(f));
    return u;
}
__device__ __forceinline__ uint32_t s2u(const void* p) {
    uint32_t a;
    asm("{ .reg .u64 t; cvta.to.shared.u64 t, %1; cvt.u32.u64 %0, t; }" : "=r"(a) : "l"(p));
    return a;
}
__device__ __forceinline__ void cp16(uint32_t dst, const void* src) {
    asm volatile("cp.async.cg.shared.global [%0], [%1], 16;" :: "r"(dst), "l"(src));
}
__device__ __forceinline__ void cp_commit() {
    asm volatile("cp.async.commit_group;" ::: "memory");
}
__device__ __forceinline__ void cp_wait1() {
    asm volatile("cp.async.wait_group 1;" ::: "memory");
}
__device__ __forceinline__ void ldsm4(unsigned (&r)[4], uint32_t a) {
    asm volatile("ldmatrix.sync.aligned.m8n8.x4.shared.b16 {%0,%1,%2,%3}, [%4];"
                 : "=r"(r[0]), "=r"(r[1]), "=r"(r[2]), "=r"(r[3]) : "r"(a));
}
__device__ __forceinline__ void mma8(float (&d)[4], const unsigned (&a)[4], const unsigned (&b)[2]) {
    asm volatile(
        "mma.sync.aligned.m16n8k8.row.col.f32.tf32.tf32.f32 "
        "{%0,%1,%2,%3},{%4,%5,%6,%7},{%8,%9},{%0,%1,%2,%3};\n"
        : "+f"(d[0]), "+f"(d[1]), "+f"(d[2]), "+f"(d[3])
        : "r"(a[0]), "r"(a[1]), "r"(a[2]), "r"(a[3]), "r"(b[0]), "r"(b[1]));
}
__device__ __forceinline__ void mma8s(float (&d)[4], const unsigned (&a)[4], unsigned b0, unsigned b1) {
    asm volatile(
        "mma.sync.aligned.m16n8k8.row.col.f32.tf32.tf32.f32 "
        "{%0,%1,%2,%3},{%4,%5,%6,%7},{%8,%9},{%0,%1,%2,%3};\n"
        : "+f"(d[0]), "+f"(d[1]), "+f"(d[2]), "+f"(d[3])
        : "r"(a[0]), "r"(a[1]), "r"(a[2]), "r"(a[3]), "r"(b0), "r"(b1));
}

// ===========================================================================
// Kernel 0: pre-round weights to tf32 AND transpose to [n][k]
// ===========================================================================
__global__ void k0_prep_t(const float* __restrict__ Wpc, const float* __restrict__ Wctx) {
    __shared__ float t[32][33];
    int b = blockIdx.x;
    int tx = threadIdx.x, ty = threadIdx.y;   // 32 x 8
    if (b < 4096) {
        int kb = (b >> 7) * 32, nb = (b & 127) * 32;
#pragma unroll
        for (int i = 0; i < 4; i++)
            t[ty + i * 8][tx] = __uint_as_float(
                f2tf(__ldg(Wpc + (size_t)(kb + ty + i * 8) * 4096 + nb + tx)));
        __syncthreads();
#pragma unroll
        for (int i = 0; i < 4; i++)
            g_wpcT[(size_t)(nb + ty + i * 8) * 1024 + kb + tx] = t[tx][ty + i * 8];
    } else {
        int bb = b - 4096;
        int kb = (bb >> 3) * 32, nb = (bb & 7) * 32;
#pragma unroll
        for (int i = 0; i < 4; i++) {
            int n = nb + tx;
            t[ty + i * 8][tx] = (n < NRELC)
                ? __uint_as_float(f2tf(__ldg(Wctx + (size_t)(kb + ty + i * 8) * NRELC + n)))
                : 0.f;
        }
        __syncthreads();
#pragma unroll
        for (int i = 0; i < 4; i++)
            g_wctxT[(size_t)(nb + ty + i * 8) * 1024 + kb + tx] = t[tx][ty + i * 8];
    }
}

// ===========================================================================
// Kernel init: out = b_rel + b_ctx + freq_table[pair_pred]
// ===========================================================================
__global__ void k_init(const int* __restrict__ pair_idx, const int* __restrict__ obj_preds,
                       const float* __restrict__ brel, const float* __restrict__ bctx,
                       const float* __restrict__ freq, float* __restrict__ out) {
    int idx = blockIdx.x * 256 + threadIdx.x;
    if (idx >= NREL * NRELC) return;
    int i = idx / NRELC;
    int c = idx - i * NRELC;
    int pp = __ldg(obj_preds + __ldg(pair_idx + 2 * i)) * NOBJC
           + __ldg(obj_preds + __ldg(pair_idx + 2 * i + 1));
    out[idx] = __ldg(brel + c) + __ldg(bctx + c) + __ldg(freq + (size_t)pp * NRELC + c);
}

// ===========================================================================
// Kernel 1: edge_rep = tf32round(edge_ctx @ W_post_emb + b)  (legacy tf32 mma)
// ===========================================================================
__device__ __forceinline__ void stA1(unsigned* __restrict__ Ab, const float4 (&ra)[4], int tid) {
#pragma unroll
    for (int i = 0; i < 4; i++) {
        int s = tid + i * 256, r = s >> 3, kq = s & 7;
        unsigned* p = Ab + r * ASTR + kq * 4;
        p[0] = f2tf(ra[i].x); p[1] = f2tf(ra[i].y); p[2] = f2tf(ra[i].z); p[3] = f2tf(ra[i].w);
    }
}
__device__ __forceinline__ void stB1(unsigned* __restrict__ Bb, const float4 (&rb)[4], int tid) {
#pragma unroll
    for (int i = 0; i < 4; i++) {
        int s = tid + i * 256, kk = s >> 5, cq = s & 31;
        unsigned* p = Bb + kk * BSTR + cq * 4;
        p[0] = f2tf(rb[i].x); p[1] = f2tf(rb[i].y); p[2] = f2tf(rb[i].z); p[3] = f2tf(rb[i].w);
    }
}
__device__ __forceinline__ void mma_tile1(float (&acc)[4][4][4], const unsigned* __restrict__ Ab,
                                          const unsigned* __restrict__ Bb, int wr, int wc, int lane) {
#pragma unroll
    for (int ks = 0; ks < 4; ks++) {
        unsigned af[4][4], bf[4][2];
#pragma unroll
        for (int tm = 0; tm < 4; tm++) {
            const unsigned* p = Ab + (wr * 64 + tm * 16 + (lane >> 2)) * ASTR + ks * 8 + (lane & 3);
            af[tm][0] = p[0]; af[tm][1] = p[8 * ASTR]; af[tm][2] = p[4]; af[tm][3] = p[8 * ASTR + 4];
        }
#pragma unroll
        for (int tn = 0; tn < 4; tn++) {
            const unsigned* p = Bb + (ks * 8 + (lane & 3)) * BSTR + wc * 32 + tn * 8 + (lane >> 2);
            bf[tn][0] = p[0]; bf[tn][1] = p[4 * BSTR];
        }
#pragma unroll
        for (int tm = 0; tm < 4; tm++)
#pragma unroll
            for (int tn = 0; tn < 4; tn++) mma8(acc[tm][tn], af[tm], bf[tn]);
    }
}

__global__ void __launch_bounds__(256, 1) k1_edge_rep(
    const float* __restrict__ A, const float* __restrict__ B, const float* __restrict__ bias) {
    extern __shared__ unsigned sm1[];
    unsigned* As = sm1;
    unsigned* Bs = sm1 + 2 * 128 * ASTR;
    const int tid = threadIdx.x, lane = tid & 31, wid = tid >> 5;
    const int wr = wid >> 2, wc = wid & 3;
    const int m0 = blockIdx.x * 128, n0 = blockIdx.y * 128;

    float acc[4][4][4];
#pragma unroll
    for (int a = 0; a < 4; a++)
#pragma unroll
        for (int b = 0; b < 4; b++)
#pragma unroll
            for (int c = 0; c < 4; c++) acc[a][b][c] = 0.f;

    float4 ra[4], rb[4];
#pragma unroll
    for (int i = 0; i < 4; i++) {
        int s = tid + i * 256;
        { int r = s >> 3, kq = s & 7;
          ra[i] = __ldg((const float4*)(A + (size_t)(m0 + r) * HID + kq * 4)); }
        { int kk = s >> 5, cq = s & 31;
          rb[i] = __ldg((const float4*)(B + (size_t)kk * 1024 + n0 + cq * 4)); }
    }
    stA1(As, ra, tid); stB1(Bs, rb, tid);
    __syncthreads();

    int buf = 0;
    for (int kt = 0; kt < 16; kt++) {
        if (kt < 15) {
            int k0 = (kt + 1) * 32;
#pragma unroll
            for (int i = 0; i < 4; i++) {
                int s = tid + i * 256;
                { int r = s >> 3, kq = s & 7;
                  ra[i] = __ldg((const float4*)(A + (size_t)(m0 + r) * HID + k0 + kq * 4)); }
                { int kk = s >> 5, cq = s & 31;
                  rb[i] = __ldg((const float4*)(B + (size_t)(k0 + kk) * 1024 + n0 + cq * 4)); }
            }
        }
        mma_tile1(acc, As + buf * 128 * ASTR, Bs + buf * 32 * BSTR, wr, wc, lane);
        if (kt < 15) { stA1(As + (buf ^ 1) * 128 * ASTR, ra, tid); stB1(Bs + (buf ^ 1) * 32 * BSTR, rb, tid); }
        __syncthreads();
        buf ^= 1;
    }

#pragma unroll
    for (int tm = 0; tm < 4; tm++) {
        int r = m0 + wr * 64 + tm * 16 + (lane >> 2);
#pragma unroll
        for (int tn = 0; tn < 4; tn++) {
            int c = n0 + wc * 32 + tn * 8 + 2 * (lane & 3);
            float2 bb = *(const float2*)(bias + c);
            float2 v0, v1;
            v0.x = __uint_as_float(f2tf(acc[tm][tn][0] + bb.x));
            v0.y = __uint_as_float(f2tf(acc[tm][tn][1] + bb.y));
            v1.x = __uint_as_float(f2tf(acc[tm][tn][2] + bb.x));
            v1.y = __uint_as_float(f2tf(acc[tm][tn][3] + bb.y));
            *(float2*)(g_edge_rep + (size_t)r * 1024 + c) = v0;
            *(float2*)(g_edge_rep + (size_t)(r + 8) * 1024 + c) = v1;
        }
    }
}

// ===========================================================================
// Kernel 2: per CTA = (m-tile, n-split of 4). ldmatrix fragment loads.
// ===========================================================================
__global__ void __launch_bounds__(256, 2) k2_main(
    const int* __restrict__ pair_idx,
    const float* __restrict__ U,
    const float* __restrict__ bpc,
    const float* __restrict__ Wrel,
    float* __restrict__ out) {
    extern __shared__ char smem[];
    const uint32_t sbu = s2u(smem);
    const float* er = g_edge_rep;

    const int tid = threadIdx.x, lane = tid & 31, wid = tid >> 5;
    const int wr = wid >> 2, wc = wid & 3;       // 2 x 4 warp grid
    const int m0 = (blockIdx.x >> 2) * 128;
    const int ns = blockIdx.x & 3;
    const int ntiles = (ns == 3) ? 9 : 8;        // split 3 also owns the virtual tile

    int* rows0 = (int*)(smem + OFFI);
    int* rows1 = rows0 + 128;

    if (tid < 128) {
        int i = m0 + tid;
        rows0[tid] = pair_idx[2 * i];
        rows1[tid] = pair_idx[2 * i + 1];
    }
    __syncthreads();

    // ldmatrix per-lane constants
    const int a_lrow = (lane & 7) + ((lane >> 3) & 1) * 8;
    const int a_lcol = (lane >> 4) * 4;
    const int b_lrow = (lane & 7) + ((lane >> 4) & 1) * 8;
    const int b_lcol = ((lane >> 3) & 1) * 4;

    // Per-thread staging constants
    int raT[2][4], aoff[4], akq[4];
#pragma unroll
    for (int i = 0; i < 4; i++) {
        int s = tid + i * 256, r = s >> 3, kq = s & 7;
        raT[0][i] = rows0[r]; raT[1][i] = rows1[r];
        aoff[i] = (r * ASTR + kq * 4) * 4;
        akq[i] = kq * 4;
    }
    int boff[4], bnn[4], bkq[4];
#pragma unroll
    for (int i = 0; i < 4; i++) {
        int s = tid + i * 256, n = s >> 3, kq = s & 7;
        bnn[i] = n; bkq[i] = kq * 4;
        boff[i] = (n * BSTR2 + kq * 4) * 4;
    }

    // Persistent partial accumulator: 128x64, warp tile 64x16 (cold spill OK)
    float acc2[4][2][4];
#pragma unroll
    for (int a = 0; a < 4; a++)
#pragma unroll
        for (int b = 0; b < 2; b++)
#pragma unroll
            for (int c = 0; c < 4; c++) acc2[a][b][c] = 0.f;

    for (int jt = 0; jt < ntiles; jt++) {
        const int nt = (jt < 8) ? (ns * 8 + jt) : 32;   // global n-tile id
        const bool real = (nt < 32);
        const float* gBT = real ? g_wpcT : g_wctxT;     // [n][1024 k]
        const int nb = real ? nt * 128 : 0;

        float acc[4][4][4];
#pragma unroll
        for (int a = 0; a < 4; a++)
#pragma unroll
            for (int b = 0; b < 4; b++)
#pragma unroll
                for (int c = 0; c < 4; c++) acc[a][b][c] = 0.f;

        // ---- prologue: stages 0,1 ----
#pragma unroll
        for (int p = 0; p < 2; p++) {
            const int k0 = p * 32;
            uint32_t ab = sbu + p * STG;
            uint32_t bb = sbu + p * STG + ABUF;
#pragma unroll
            for (int i = 0; i < 4; i++)
                cp16(ab + aoff[i], er + (size_t)raT[0][i] * 1024 + k0 + akq[i]);
#pragma unroll
            for (int i = 0; i < 4; i++)
                cp16(bb + boff[i], gBT + (size_t)(nb + bnn[i]) * 1024 + k0 + bkq[i]);
            cp_commit();
        }

        // ---- main loop: 32 chunks of BK=32 ----
        for (int kc = 0; kc < 32; kc++) {
            cp_wait1();
            __syncthreads();
            if (kc < 30) {
                const int k0 = (kc + 2) * 32;
                const int st = (kc + 2) % 3;
                const int h = (k0 >= HID) ? 1 : 0;
                uint32_t ab = sbu + st * STG;
                uint32_t bb = sbu + st * STG + ABUF;
#pragma unroll
                for (int i = 0; i < 4; i++)
                    cp16(ab + aoff[i], er + (size_t)raT[h][i] * 1024 + k0 + akq[i]);
#pragma unroll
                for (int i = 0; i < 4; i++)
                    cp16(bb + boff[i], gBT + (size_t)(nb + bnn[i]) * 1024 + k0 + bkq[i]);
            }
            cp_commit();

            const int st = kc % 3;
            const uint32_t Ab = sbu + st * STG;
            const uint32_t Bb = sbu + st * STG + ABUF;
#pragma unroll
            for (int ks = 0; ks < 4; ks++) {
                unsigned af[4][4], bf2[2][4];
#pragma unroll
                for (int tm = 0; tm < 4; tm++)
                    ldsm4(af[tm], Ab + (uint32_t)(((wr * 64 + tm * 16 + a_lrow) * ASTR
                                                   + ks * 8 + a_lcol) * 4));
#pragma unroll
                for (int t2 = 0; t2 < 2; t2++)
                    ldsm4(bf2[t2], Bb + (uint32_t)(((wc * 32 + t2 * 16 + b_lrow) * BSTR2
                                                    + ks * 8 + b_lcol) * 4));
#pragma unroll
                for (int tm = 0; tm < 4; tm++)
#pragma unroll
                    for (int tn = 0; tn < 4; tn++)
                        mma8s(acc[tm][tn], af[tm],
                              bf2[tn >> 1][(tn & 1) * 2], bf2[tn >> 1][(tn & 1) * 2 + 1]);
            }
        }
        __syncthreads();   // stages consumed; region reused as V/W

        // ---- epilogue: V = (G + bpc) * U  (or V = G for virtual tile) ----
        unsigned* Vs = (unsigned*)(smem + OFFV);
        unsigned* Ws = (unsigned*)(smem + OFFW);
        const int n0 = nt * 128;
#pragma unroll
        for (int tm = 0; tm < 4; tm++) {
            int rl = wr * 64 + tm * 16 + (lane >> 2);
            if (real) {
                const float* u0p = U + (size_t)(m0 + rl) * POOL + n0;
                const float* u1p = u0p + 8 * POOL;
#pragma unroll
                for (int tn = 0; tn < 4; tn++) {
                    int vcol = wc * 32 + tn * 8 + 2 * (lane & 3);
                    float2 bb = *(const float2*)(bpc + n0 + vcol);
                    float2 u0 = __ldg((const float2*)(u0p + vcol));
                    float2 u1 = __ldg((const float2*)(u1p + vcol));
                    Vs[rl * VSTR + vcol]           = f2tf((acc[tm][tn][0] + bb.x) * u0.x);
                    Vs[rl * VSTR + vcol + 1]       = f2tf((acc[tm][tn][1] + bb.y) * u0.y);
                    Vs[(rl + 8) * VSTR + vcol]     = f2tf((acc[tm][tn][2] + bb.x) * u1.x);
                    Vs[(rl + 8) * VSTR + vcol + 1] = f2tf((acc[tm][tn][3] + bb.y) * u1.y);
                }
            } else {
#pragma unroll
                for (int tn = 0; tn < 4; tn++) {
                    int vcol = wc * 32 + tn * 8 + 2 * (lane & 3);
                    Vs[rl * VSTR + vcol]           = f2tf(acc[tm][tn][0]);
                    Vs[rl * VSTR + vcol + 1]       = f2tf(acc[tm][tn][1]);
                    Vs[(rl + 8) * VSTR + vcol]     = f2tf(acc[tm][tn][2]);
                    Vs[(rl + 8) * VSTR + vcol + 1] = f2tf(acc[tm][tn][3]);
                }
            }
        }
        // Ws: [128 k][64 n] = Wrel chunk (or identity for the virtual tile)
        if (real) {
#pragma unroll 4
            for (int i = 0; i < 32; i++) {
                int s = tid + i * 256, k = s >> 6, c = s & 63;
                float v = (c < NRELC) ? __ldg(Wrel + (size_t)(n0 + k) * NRELC + c) : 0.f;
                Ws[k * WSTR + c] = f2tf(v);
            }
        } else {
#pragma unroll 4
            for (int i = 0; i < 32; i++) {
                int s = tid + i * 256, k = s >> 6, c = s & 63;
                Ws[k * WSTR + c] = (k == c && c < NRELC) ? 0x3F800000u : 0u;
            }
        }
        __syncthreads();

        // ---- acc2 += V(128x128) @ Ws(128x64) ----
#pragma unroll
        for (int kk = 0; kk < 16; kk++) {
            unsigned af[4][4], bf[2][2];
#pragma unroll
            for (int tm = 0; tm < 4; tm++) {
                const unsigned* p = Vs + (wr * 64 + tm * 16 + (lane >> 2)) * VSTR + kk * 8 + (lane & 3);
                af[tm][0] = p[0]; af[tm][1] = p[8 * VSTR];
                af[tm][2] = p[4]; af[tm][3] = p[8 * VSTR + 4];
            }
#pragma unroll
            for (int tn = 0; tn < 2; tn++) {
                const unsigned* p = Ws + (kk * 8 + (lane & 3)) * WSTR + wc * 16 + tn * 8 + (lane >> 2);
                bf[tn][0] = p[0]; bf[tn][1] = p[4 * WSTR];
            }
#pragma unroll
            for (int tm = 0; tm < 4; tm++)
#pragma unroll
                for (int tn = 0; tn < 2; tn++)
                    mma8(acc2[tm][tn], af[tm], bf[tn]);
        }
        __syncthreads();
    }

    // ---- combine partials: atomicAdd into pre-initialized out ----
#pragma unroll
    for (int tm = 0; tm < 4; tm++) {
        int rl = wr * 64 + tm * 16 + (lane >> 2);
#pragma unroll
        for (int tn = 0; tn < 2; tn++) {
            int c = wc * 16 + tn * 8 + 2 * (lane & 3);
#pragma unroll
            for (int q = 0; q < 4; q++) {
                int row = rl + ((q >= 2) ? 8 : 0);
                int col = c + (q & 1);
                if (col < NRELC)
                    atomicAdd(out + (size_t)(m0 + row) * NRELC + col, acc2[tm][tn][q]);
            }
        }
    }
}

// ===========================================================================
// Launch
// ===========================================================================
extern "C" void kernel_launch(void* const* d_in, const int* in_sizes, int n_in,
                              void* d_out, int out_size) {
    (void)in_sizes; (void)n_in; (void)out_size;
    const float* edge_ctx  = (const float*)d_in[0];
    const int*   obj_preds = (const int*)d_in[1];
    const int*   pair_idx  = (const int*)d_in[2];
    const float* U         = (const float*)d_in[3];
    const float* Wpe       = (const float*)d_in[4];
    const float* bpe       = (const float*)d_in[5];
    const float* Wpc       = (const float*)d_in[6];
    const float* bpc       = (const float*)d_in[7];
    const float* Wrel      = (const float*)d_in[8];
    const float* brel      = (const float*)d_in[9];
    const float* Wctx      = (const float*)d_in[10];
    const float* bctx      = (const float*)d_in[11];
    const float* freq      = (const float*)d_in[12];
    float* out = (float*)d_out;

    cudaFuncSetAttribute(k1_edge_rep, cudaFuncAttributeMaxDynamicSharedMemorySize, K1_SMEM);
    cudaFuncSetAttribute(k2_main,     cudaFuncAttributeMaxDynamicSharedMemorySize, K2S);

    k0_prep_t<<<4096 + 256, dim3(32, 8)>>>(Wpc, Wctx);
    k_init<<<(NREL * NRELC + 255) / 256, 256>>>(pair_idx, obj_preds, brel, bctx, freq, out);
    k1_edge_rep<<<dim3(64, 8), 256, K1_SMEM>>>(edge_ctx, Wpe, bpe);
    k2_main<<<2048, 256, K2S>>>(pair_idx, U, bpc, Wrel, out);
}

// round 16
// speedup vs baseline: 1.0232x; 1.0232x over previous
#include <cuda_runtime.h>
#include <cstdint>
#include <cstddef>

// Problem constants
#define HID    512
#define NOBJC  151
#define NRELC  51
#define POOL   4096
#define NREL   65536

// ---------------- k1 (edge_rep) constants ----------------
#define ASTR 36
#define BSTR 136
#define K1_SMEM ((2*128*ASTR + 2*32*BSTR) * 4)

// ---------------- k2 constants ----------------
// BM=128, BN=128, BK=32, 3-stage cp.async, 128 threads (4 warps, 2x2),
// warp tile 64x64 (acc[4][8][4] = 128 regs), ldmatrix loads. 2 CTAs/SM.
// A stage: [128 m][32 k] stride 36; B stage: [128 n][32 k] stride 36.
#define BSTR2 36
#define ABUF (128*ASTR*4)          // 18432 B
#define BBUF (128*BSTR2*4)         // 18432 B
#define STG  (ABUF + BBUF)         // 36864
#define VSTR 132
#define WSTR 72
// V/W union the stage region (time-disjoint):
#define OFFV 0
#define OFFW (128*VSTR*4)          // 67584 ; V+W = 104448 <= 3*STG = 110592
#define OFFI (3*STG)               // 110592
#define K2S  (OFFI + 2*128*4)      // 111616  (x2 CTAs = 223232 <= 228KB/SM)

// Prepared (pre-rounded tf32) buffers
__device__ float g_edge_rep[(size_t)8192 * 1024];   // tf32-rounded, [row][k]
__device__ float g_wpcT[(size_t)4096 * 1024];       // tf32 W_post_cat, TRANSPOSED [n][k]
__device__ float g_wctxT[(size_t)256 * 1024];       // tf32 W_ctx, padded, TRANSPOSED [n][k]

// ---------------------------------------------------------------------------
__device__ __forceinline__ unsigned f2tf(float f) {
    unsigned u;
    asm("cvt.rna.tf32.f32 %0, %1;" : "=r"(u) : "f"(f));
    return u;
}
__device__ __forceinline__ uint32_t s2u(const void* p) {
    uint32_t a;
    asm("{ .reg .u64 t; cvta.to.shared.u64 t, %1; cvt.u32.u64 %0, t; }" : "=r"(a) : "l"(p));
    return a;
}
__device__ __forceinline__ void cp16(uint32_t dst, const void* src) {
    asm volatile("cp.async.cg.shared.global [%0], [%1], 16;" :: "r"(dst), "l"(src));
}
__device__ __forceinline__ void cp_commit() {
    asm volatile("cp.async.commit_group;" ::: "memory");
}
__device__ __forceinline__ void cp_wait1() {
    asm volatile("cp.async.wait_group 1;" ::: "memory");
}
__device__ __forceinline__ void ldsm4(unsigned (&r)[4], uint32_t a) {
    asm volatile("ldmatrix.sync.aligned.m8n8.x4.shared.b16 {%0,%1,%2,%3}, [%4];"
                 : "=r"(r[0]), "=r"(r[1]), "=r"(r[2]), "=r"(r[3]) : "r"(a));
}
__device__ __forceinline__ void mma8(float (&d)[4], const unsigned (&a)[4], const unsigned (&b)[2]) {
    asm volatile(
        "mma.sync.aligned.m16n8k8.row.col.f32.tf32.tf32.f32 "
        "{%0,%1,%2,%3},{%4,%5,%6,%7},{%8,%9},{%0,%1,%2,%3};\n"
        : "+f"(d[0]), "+f"(d[1]), "+f"(d[2]), "+f"(d[3])
        : "r"(a[0]), "r"(a[1]), "r"(a[2]), "r"(a[3]), "r"(b[0]), "r"(b[1]));
}
__device__ __forceinline__ void mma8s(float (&d)[4], const unsigned (&a)[4], unsigned b0, unsigned b1) {
    asm volatile(
        "mma.sync.aligned.m16n8k8.row.col.f32.tf32.tf32.f32 "
        "{%0,%1,%2,%3},{%4,%5,%6,%7},{%8,%9},{%0,%1,%2,%3};\n"
        : "+f"(d[0]), "+f"(d[1]), "+f"(d[2]), "+f"(d[3])
        : "r"(a[0]), "r"(a[1]), "r"(a[2]), "r"(a[3]), "r"(b0), "r"(b1));
}

// ===========================================================================
// Kernel 0: pre-round weights to tf32 AND transpose to [n][k]
// ===========================================================================
__global__ void k0_prep_t(const float* __restrict__ Wpc, const float* __restrict__ Wctx) {
    __shared__ float t[32][33];
    int b = blockIdx.x;
    int tx = threadIdx.x, ty = threadIdx.y;   // 32 x 8
    if (b < 4096) {
        int kb = (b >> 7) * 32, nb = (b & 127) * 32;
#pragma unroll
        for (int i = 0; i < 4; i++)
            t[ty + i * 8][tx] = __uint_as_float(
                f2tf(__ldg(Wpc + (size_t)(kb + ty + i * 8) * 4096 + nb + tx)));
        __syncthreads();
#pragma unroll
        for (int i = 0; i < 4; i++)
            g_wpcT[(size_t)(nb + ty + i * 8) * 1024 + kb + tx] = t[tx][ty + i * 8];
    } else {
        int bb = b - 4096;
        int kb = (bb >> 3) * 32, nb = (bb & 7) * 32;
#pragma unroll
        for (int i = 0; i < 4; i++) {
            int n = nb + tx;
            t[ty + i * 8][tx] = (n < NRELC)
                ? __uint_as_float(f2tf(__ldg(Wctx + (size_t)(kb + ty + i * 8) * NRELC + n)))
                : 0.f;
        }
        __syncthreads();
#pragma unroll
        for (int i = 0; i < 4; i++)
            g_wctxT[(size_t)(nb + ty + i * 8) * 1024 + kb + tx] = t[tx][ty + i * 8];
    }
}

// ===========================================================================
// Kernel init: out = b_rel + b_ctx + freq_table[pair_pred]
// ===========================================================================
__global__ void k_init(const int* __restrict__ pair_idx, const int* __restrict__ obj_preds,
                       const float* __restrict__ brel, const float* __restrict__ bctx,
                       const float* __restrict__ freq, float* __restrict__ out) {
    int idx = blockIdx.x * 256 + threadIdx.x;
    if (idx >= NREL * NRELC) return;
    int i = idx / NRELC;
    int c = idx - i * NRELC;
    int pp = __ldg(obj_preds + __ldg(pair_idx + 2 * i)) * NOBJC
           + __ldg(obj_preds + __ldg(pair_idx + 2 * i + 1));
    out[idx] = __ldg(brel + c) + __ldg(bctx + c) + __ldg(freq + (size_t)pp * NRELC + c);
}

// ===========================================================================
// Kernel 1: edge_rep = tf32round(edge_ctx @ W_post_emb + b)  (legacy tf32 mma)
// ===========================================================================
__device__ __forceinline__ void stA1(unsigned* __restrict__ Ab, const float4 (&ra)[4], int tid) {
#pragma unroll
    for (int i = 0; i < 4; i++) {
        int s = tid + i * 256, r = s >> 3, kq = s & 7;
        unsigned* p = Ab + r * ASTR + kq * 4;
        p[0] = f2tf(ra[i].x); p[1] = f2tf(ra[i].y); p[2] = f2tf(ra[i].z); p[3] = f2tf(ra[i].w);
    }
}
__device__ __forceinline__ void stB1(unsigned* __restrict__ Bb, const float4 (&rb)[4], int tid) {
#pragma unroll
    for (int i = 0; i < 4; i++) {
        int s = tid + i * 256, kk = s >> 5, cq = s & 31;
        unsigned* p = Bb + kk * BSTR + cq * 4;
        p[0] = f2tf(rb[i].x); p[1] = f2tf(rb[i].y); p[2] = f2tf(rb[i].z); p[3] = f2tf(rb[i].w);
    }
}
__device__ __forceinline__ void mma_tile1(float (&acc)[4][4][4], const unsigned* __restrict__ Ab,
                                          const unsigned* __restrict__ Bb, int wr, int wc, int lane) {
#pragma unroll
    for (int ks = 0; ks < 4; ks++) {
        unsigned af[4][4], bf[4][2];
#pragma unroll
        for (int tm = 0; tm < 4; tm++) {
            const unsigned* p = Ab + (wr * 64 + tm * 16 + (lane >> 2)) * ASTR + ks * 8 + (lane & 3);
            af[tm][0] = p[0]; af[tm][1] = p[8 * ASTR]; af[tm][2] = p[4]; af[tm][3] = p[8 * ASTR + 4];
        }
#pragma unroll
        for (int tn = 0; tn < 4; tn++) {
            const unsigned* p = Bb + (ks * 8 + (lane & 3)) * BSTR + wc * 32 + tn * 8 + (lane >> 2);
            bf[tn][0] = p[0]; bf[tn][1] = p[4 * BSTR];
        }
#pragma unroll
        for (int tm = 0; tm < 4; tm++)
#pragma unroll
            for (int tn = 0; tn < 4; tn++) mma8(acc[tm][tn], af[tm], bf[tn]);
    }
}

__global__ void __launch_bounds__(256, 1) k1_edge_rep(
    const float* __restrict__ A, const float* __restrict__ B, const float* __restrict__ bias) {
    extern __shared__ unsigned sm1[];
    unsigned* As = sm1;
    unsigned* Bs = sm1 + 2 * 128 * ASTR;
    const int tid = threadIdx.x, lane = tid & 31, wid = tid >> 5;
    const int wr = wid >> 2, wc = wid & 3;
    const int m0 = blockIdx.x * 128, n0 = blockIdx.y * 128;

    float acc[4][4][4];
#pragma unroll
    for (int a = 0; a < 4; a++)
#pragma unroll
        for (int b = 0; b < 4; b++)
#pragma unroll
            for (int c = 0; c < 4; c++) acc[a][b][c] = 0.f;

    float4 ra[4], rb[4];
#pragma unroll
    for (int i = 0; i < 4; i++) {
        int s = tid + i * 256;
        { int r = s >> 3, kq = s & 7;
          ra[i] = __ldg((const float4*)(A + (size_t)(m0 + r) * HID + kq * 4)); }
        { int kk = s >> 5, cq = s & 31;
          rb[i] = __ldg((const float4*)(B + (size_t)kk * 1024 + n0 + cq * 4)); }
    }
    stA1(As, ra, tid); stB1(Bs, rb, tid);
    __syncthreads();

    int buf = 0;
    for (int kt = 0; kt < 16; kt++) {
        if (kt < 15) {
            int k0 = (kt + 1) * 32;
#pragma unroll
            for (int i = 0; i < 4; i++) {
                int s = tid + i * 256;
                { int r = s >> 3, kq = s & 7;
                  ra[i] = __ldg((const float4*)(A + (size_t)(m0 + r) * HID + k0 + kq * 4)); }
                { int kk = s >> 5, cq = s & 31;
                  rb[i] = __ldg((const float4*)(B + (size_t)(k0 + kk) * 1024 + n0 + cq * 4)); }
            }
        }
        mma_tile1(acc, As + buf * 128 * ASTR, Bs + buf * 32 * BSTR, wr, wc, lane);
        if (kt < 15) { stA1(As + (buf ^ 1) * 128 * ASTR, ra, tid); stB1(Bs + (buf ^ 1) * 32 * BSTR, rb, tid); }
        __syncthreads();
        buf ^= 1;
    }

#pragma unroll
    for (int tm = 0; tm < 4; tm++) {
        int r = m0 + wr * 64 + tm * 16 + (lane >> 2);
#pragma unroll
        for (int tn = 0; tn < 4; tn++) {
            int c = n0 + wc * 32 + tn * 8 + 2 * (lane & 3);
            float2 bb = *(const float2*)(bias + c);
            float2 v0, v1;
            v0.x = __uint_as_float(f2tf(acc[tm][tn][0] + bb.x));
            v0.y = __uint_as_float(f2tf(acc[tm][tn][1] + bb.y));
            v1.x = __uint_as_float(f2tf(acc[tm][tn][2] + bb.x));
            v1.y = __uint_as_float(f2tf(acc[tm][tn][3] + bb.y));
            *(float2*)(g_edge_rep + (size_t)r * 1024 + c) = v0;
            *(float2*)(g_edge_rep + (size_t)(r + 8) * 1024 + c) = v1;
        }
    }
}

// ===========================================================================
// Kernel 2: per CTA = (m-tile, n-split of 4). 128 threads, 4 warps 2x2,
// warp tile 64x64. 2 CTAs/SM.
// ===========================================================================
__global__ void __launch_bounds__(128) k2_main(
    const int* __restrict__ pair_idx,
    const float* __restrict__ U,
    const float* __restrict__ bpc,
    const float* __restrict__ Wrel,
    float* __restrict__ out) {
    extern __shared__ char smem[];
    const uint32_t sbu = s2u(smem);
    const float* er = g_edge_rep;

    const int tid = threadIdx.x, lane = tid & 31, wid = tid >> 5;
    const int wr = wid >> 1, wc = wid & 1;       // 2 x 2 warp grid
    const int m0 = (blockIdx.x >> 2) * 128;
    const int ns = blockIdx.x & 3;
    const int ntiles = (ns == 3) ? 9 : 8;        // split 3 also owns the virtual tile

    int* rows0 = (int*)(smem + OFFI);
    int* rows1 = rows0 + 128;

    {
        int i = m0 + tid;
        rows0[tid] = pair_idx[2 * i];
        rows1[tid] = pair_idx[2 * i + 1];
    }
    __syncthreads();

    // ldmatrix per-lane constants
    const int a_lrow = (lane & 7) + ((lane >> 3) & 1) * 8;
    const int a_lcol = (lane >> 4) * 4;
    const int b_lrow = (lane & 7) + ((lane >> 4) & 1) * 8;
    const int b_lcol = ((lane >> 3) & 1) * 4;

    // Staging constants: thread handles s = tid + i*128, i<8; kq = tid&7 const.
    const int skq4 = (tid & 7) * 4;              // k offset in floats
    const int r0i = tid >> 3;                    // row base, step 16 per i
    int raT[2][8];
#pragma unroll
    for (int i = 0; i < 8; i++) {
        raT[0][i] = rows0[r0i + i * 16];
        raT[1][i] = rows1[r0i + i * 16];
    }
    const uint32_t abase0 = (uint32_t)(r0i * ASTR + skq4) * 4;   // + i*16*ASTR*4
    const uint32_t bbase0 = (uint32_t)(r0i * BSTR2 + skq4) * 4;  // + i*16*BSTR2*4

    // Persistent second-GEMM accumulator: 128x64, warp tile 64x32 (2x2)
    float acc2[4][4][4];
#pragma unroll
    for (int a = 0; a < 4; a++)
#pragma unroll
        for (int b = 0; b < 4; b++)
#pragma unroll
            for (int c = 0; c < 4; c++) acc2[a][b][c] = 0.f;

    for (int jt = 0; jt < ntiles; jt++) {
        const int nt = (jt < 8) ? (ns * 8 + jt) : 32;   // global n-tile id
        const bool real = (nt < 32);
        const float* gBT = real ? g_wpcT : g_wctxT;     // [n][1024 k]
        const int nb = real ? nt * 128 : 0;

        float acc[4][8][4];
#pragma unroll
        for (int a = 0; a < 4; a++)
#pragma unroll
            for (int b = 0; b < 8; b++)
#pragma unroll
                for (int c = 0; c < 4; c++) acc[a][b][c] = 0.f;

        // ---- prologue: stages 0,1 ----
#pragma unroll
        for (int p = 0; p < 2; p++) {
            const int k0 = p * 32;
            uint32_t ab = sbu + p * STG + abase0;
            uint32_t bb = sbu + p * STG + ABUF + bbase0;
#pragma unroll
            for (int i = 0; i < 8; i++)
                cp16(ab + i * (16 * ASTR * 4), er + (size_t)raT[0][i] * 1024 + k0 + skq4);
#pragma unroll
            for (int i = 0; i < 8; i++)
                cp16(bb + i * (16 * BSTR2 * 4), gBT + (size_t)(nb + r0i + i * 16) * 1024 + k0 + skq4);
            cp_commit();
        }

        // ---- main loop: 32 chunks of BK=32 ----
        for (int kc = 0; kc < 32; kc++) {
            cp_wait1();
            __syncthreads();
            if (kc < 30) {
                const int k0 = (kc + 2) * 32;
                const int st = (kc + 2) % 3;
                const int h = (k0 >= HID) ? 1 : 0;
                uint32_t ab = sbu + st * STG + abase0;
                uint32_t bb = sbu + st * STG + ABUF + bbase0;
#pragma unroll
                for (int i = 0; i < 8; i++)
                    cp16(ab + i * (16 * ASTR * 4), er + (size_t)raT[h][i] * 1024 + k0 + skq4);
#pragma unroll
                for (int i = 0; i < 8; i++)
                    cp16(bb + i * (16 * BSTR2 * 4), gBT + (size_t)(nb + r0i + i * 16) * 1024 + k0 + skq4);
            }
            cp_commit();

            const int st = kc % 3;
            const uint32_t Ab = sbu + st * STG;
            const uint32_t Bb = sbu + st * STG + ABUF;
#pragma unroll
            for (int ks = 0; ks < 4; ks++) {
                unsigned af[4][4], bf[4][4];
#pragma unroll
                for (int tm = 0; tm < 4; tm++)
                    ldsm4(af[tm], Ab + (uint32_t)(((wr * 64 + tm * 16 + a_lrow) * ASTR
                                                   + ks * 8 + a_lcol) * 4));
#pragma unroll
                for (int tb = 0; tb < 4; tb++)
                    ldsm4(bf[tb], Bb + (uint32_t)(((wc * 64 + tb * 16 + b_lrow) * BSTR2
                                                   + ks * 8 + b_lcol) * 4));
#pragma unroll
                for (int tm = 0; tm < 4; tm++)
#pragma unroll
                    for (int tn = 0; tn < 8; tn++)
                        mma8s(acc[tm][tn], af[tm],
                              bf[tn >> 1][(tn & 1) * 2], bf[tn >> 1][(tn & 1) * 2 + 1]);
            }
        }
        __syncthreads();   // stages consumed; region reused as V/W

        // ---- epilogue: V = (G + bpc) * U  (or V = G for virtual tile) ----
        unsigned* Vs = (unsigned*)(smem + OFFV);
        unsigned* Ws = (unsigned*)(smem + OFFW);
        const int n0 = nt * 128;
#pragma unroll
        for (int tm = 0; tm < 4; tm++) {
            int rl = wr * 64 + tm * 16 + (lane >> 2);
            if (real) {
                const float* u0p = U + (size_t)(m0 + rl) * POOL + n0;
                const float* u1p = u0p + 8 * POOL;
#pragma unroll
                for (int tn = 0; tn < 8; tn++) {
                    int vcol = wc * 64 + tn * 8 + 2 * (lane & 3);
                    float2 bb = *(const float2*)(bpc + n0 + vcol);
                    float2 u0 = __ldg((const float2*)(u0p + vcol));
                    float2 u1 = __ldg((const float2*)(u1p + vcol));
                    Vs[rl * VSTR + vcol]           = f2tf((acc[tm][tn][0] + bb.x) * u0.x);
                    Vs[rl * VSTR + vcol + 1]       = f2tf((acc[tm][tn][1] + bb.y) * u0.y);
                    Vs[(rl + 8) * VSTR + vcol]     = f2tf((acc[tm][tn][2] + bb.x) * u1.x);
                    Vs[(rl + 8) * VSTR + vcol + 1] = f2tf((acc[tm][tn][3] + bb.y) * u1.y);
                }
            } else {
#pragma unroll
                for (int tn = 0; tn < 8; tn++) {
                    int vcol = wc * 64 + tn * 8 + 2 * (lane & 3);
                    Vs[rl * VSTR + vcol]           = f2tf(acc[tm][tn][0]);
                    Vs[rl * VSTR + vcol + 1]       = f2tf(acc[tm][tn][1]);
                    Vs[(rl + 8) * VSTR + vcol]     = f2tf(acc[tm][tn][2]);
                    Vs[(rl + 8) * VSTR + vcol + 1] = f2tf(acc[tm][tn][3]);
                }
            }
        }
        // Ws: [128 k][64 n] = Wrel chunk (or identity for the virtual tile)
        if (real) {
#pragma unroll 4
            for (int i = 0; i < 64; i++) {
                int s = tid + i * 128, k = s >> 6, c = s & 63;
                float v = (c < NRELC) ? __ldg(Wrel + (size_t)(n0 + k) * NRELC + c) : 0.f;
                Ws[k * WSTR + c] = f2tf(v);
            }
        } else {
#pragma unroll 4
            for (int i = 0; i < 64; i++) {
                int s = tid + i * 128, k = s >> 6, c = s & 63;
                Ws[k * WSTR + c] = (k == c && c < NRELC) ? 0x3F800000u : 0u;
            }
        }
        __syncthreads();

        // ---- acc2 += V(128x128) @ Ws(128x64); warp tile 64x32 (2x2) ----
#pragma unroll
        for (int kk = 0; kk < 16; kk++) {
            unsigned af[4][4], bf[4][2];
#pragma unroll
            for (int tm = 0; tm < 4; tm++)
                ldsm4(af[tm], (uint32_t)(sbu + OFFV
                      + ((wr * 64 + tm * 16 + a_lrow) * VSTR + kk * 8 + a_lcol) * 4));
#pragma unroll
            for (int tn = 0; tn < 4; tn++) {
                const unsigned* p = Ws + (kk * 8 + (lane & 3)) * WSTR + wc * 32 + tn * 8 + (lane >> 2);
                bf[tn][0] = p[0]; bf[tn][1] = p[4 * WSTR];
            }
#pragma unroll
            for (int tm = 0; tm < 4; tm++)
#pragma unroll
                for (int tn = 0; tn < 4; tn++)
                    mma8(acc2[tm][tn], af[tm], bf[tn]);
        }
        __syncthreads();
    }

    // ---- combine partials: atomicAdd into pre-initialized out ----
#pragma unroll
    for (int tm = 0; tm < 4; tm++) {
        int rl = wr * 64 + tm * 16 + (lane >> 2);
#pragma unroll
        for (int tn = 0; tn < 4; tn++) {
            int c = wc * 32 + tn * 8 + 2 * (lane & 3);
#pragma unroll
            for (int q = 0; q < 4; q++) {
                int row = rl + ((q >= 2) ? 8 : 0);
                int col = c + (q & 1);
                if (col < NRELC)
                    atomicAdd(out + (size_t)(m0 + row) * NRELC + col, acc2[tm][tn][q]);
            }
        }
    }
}

// ===========================================================================
// Launch
// ===========================================================================
extern "C" void kernel_launch(void* const* d_in, const int* in_sizes, int n_in,
                              void* d_out, int out_size) {
    (void)in_sizes; (void)n_in; (void)out_size;
    const float* edge_ctx  = (const float*)d_in[0];
    const int*   obj_preds = (const int*)d_in[1];
    const int*   pair_idx  = (const int*)d_in[2];
    const float* U         = (const float*)d_in[3];
    const float* Wpe       = (const float*)d_in[4];
    const float* bpe       = (const float*)d_in[5];
    const float* Wpc       = (const float*)d_in[6];
    const float* bpc       = (const float*)d_in[7];
    const float* Wrel      = (const float*)d_in[8];
    const float* brel      = (const float*)d_in[9];
    const float* Wctx      = (const float*)d_in[10];
    const float* bctx      = (const float*)d_in[11];
    const float* freq      = (const float*)d_in[12];
    float* out = (float*)d_out;

    cudaFuncSetAttribute(k1_edge_rep, cudaFuncAttributeMaxDynamicSharedMemorySize, K1_SMEM);
    cudaFuncSetAttribute(k2_main,     cudaFuncAttributeMaxDynamicSharedMemorySize, K2S);

    k0_prep_t<<<4096 + 256, dim3(32, 8)>>>(Wpc, Wctx);
    k_init<<<(NREL * NRELC + 255) / 256, 256>>>(pair_idx, obj_preds, brel, bctx, freq, out);
    k1_edge_rep<<<dim3(64, 8), 256, K1_SMEM>>>(edge_ctx, Wpe, bpe);
    k2_main<<<2048, 128, K2S>>>(pair_idx, U, bpc, Wrel, out);
}

// round 17
// speedup vs baseline: 2.1377x; 2.0892x over previous
#include <cuda_runtime.h>
#include <cstdint>
#include <cstddef>

// Problem constants
#define HID    512
#define NOBJC  151
#define NRELC  51
#define POOL   4096
#define NREL   65536

// ---------------- k1 (edge_rep) constants ----------------
#define ASTR 36
#define BSTR 136
#define K1_SMEM ((2*128*ASTR + 2*32*BSTR) * 4)

// ---------------- kH constants (R16-style mainloop) ----------------
#define BSTR2 36
#define ABUF (128*ASTR*4)          // 18432 B
#define BBUF (128*BSTR2*4)         // 18432 B
#define STG  (ABUF + BBUF)         // 36864
#define KH_SMEM (3*STG)            // 110592

// ---------------- k2b constants ----------------
#define V2STR 68
#define W2STR 72
#define VBUF  (128*V2STR*4)        // 34816
#define WBUF2 (64*W2STR*4)         // 18432
#define OFFW2 (2*VBUF)             // 69632
#define OFFI2 (OFFW2 + 2*WBUF2)    // 106496
#define K2BS  (OFFI2 + 2*128*4)    // 107520  (2 CTAs/SM)

// Prepared buffers
__device__ float g_edge_rep[(size_t)8192 * 1024];   // tf32-rounded, [row][k]
__device__ float g_wpcT[(size_t)4096 * 1024];       // tf32 W_post_cat, TRANSPOSED [n][k]
__device__ float g_wctxT[(size_t)256 * 1024];       // tf32 W_ctx, padded, TRANSPOSED [n][k]
__device__ float g_wrelp[(size_t)4096 * 64];        // tf32 W_rel, padded [n][64]
__device__ float g_H[(size_t)8192 * 4096];          // head_rep @ Wpc_top   (fp32)
__device__ float g_T[(size_t)8192 * 4096];          // tail_rep @ Wpc_bot   (fp32)
__device__ float g_Hc[(size_t)8192 * 128];          // head_rep @ Wctx_top  (fp32)
__device__ float g_Tc[(size_t)8192 * 128];          // tail_rep @ Wctx_bot  (fp32)

// ---------------------------------------------------------------------------
__device__ __forceinline__ unsigned f2tf(float f) {
    unsigned u;
    asm("cvt.rna.tf32.f32 %0, %1;" : "=r"(u) : "f"(f));
    return u;
}
__device__ __forceinline__ uint32_t s2u(const void* p) {
    uint32_t a;
    asm("{ .reg .u64 t; cvta.to.shared.u64 t, %1; cvt.u32.u64 %0, t; }" : "=r"(a) : "l"(p));
    return a;
}
__device__ __forceinline__ void cp16(uint32_t dst, const void* src) {
    asm volatile("cp.async.cg.shared.global [%0], [%1], 16;" :: "r"(dst), "l"(src));
}
__device__ __forceinline__ void cp_commit() {
    asm volatile("cp.async.commit_group;" ::: "memory");
}
__device__ __forceinline__ void cp_wait1() {
    asm volatile("cp.async.wait_group 1;" ::: "memory");
}
__device__ __forceinline__ void cp_wait0() {
    asm volatile("cp.async.wait_group 0;" ::: "memory");
}
__device__ __forceinline__ void ldsm4(unsigned (&r)[4], uint32_t a) {
    asm volatile("ldmatrix.sync.aligned.m8n8.x4.shared.b16 {%0,%1,%2,%3}, [%4];"
                 : "=r"(r[0]), "=r"(r[1]), "=r"(r[2]), "=r"(r[3]) : "r"(a));
}
__device__ __forceinline__ void mma8(float (&d)[4], const unsigned (&a)[4], const unsigned (&b)[2]) {
    asm volatile(
        "mma.sync.aligned.m16n8k8.row.col.f32.tf32.tf32.f32 "
        "{%0,%1,%2,%3},{%4,%5,%6,%7},{%8,%9},{%0,%1,%2,%3};\n"
        : "+f"(d[0]), "+f"(d[1]), "+f"(d[2]), "+f"(d[3])
        : "r"(a[0]), "r"(a[1]), "r"(a[2]), "r"(a[3]), "r"(b[0]), "r"(b[1]));
}
__device__ __forceinline__ void mma8s(float (&d)[4], const unsigned (&a)[4], unsigned b0, unsigned b1) {
    asm volatile(
        "mma.sync.aligned.m16n8k8.row.col.f32.tf32.tf32.f32 "
        "{%0,%1,%2,%3},{%4,%5,%6,%7},{%8,%9},{%0,%1,%2,%3};\n"
        : "+f"(d[0]), "+f"(d[1]), "+f"(d[2]), "+f"(d[3])
        : "r"(a[0]), "r"(a[1]), "r"(a[2]), "r"(a[3]), "r"(b0), "r"(b1));
}

// ===========================================================================
// Kernel 0: pre-round weights to tf32; transpose Wpc/Wctx to [n][k]; pad Wrel
// ===========================================================================
__global__ void k0_prep_t(const float* __restrict__ Wpc, const float* __restrict__ Wctx,
                          const float* __restrict__ Wrel) {
    __shared__ float t[32][33];
    int b = blockIdx.x;
    int tx = threadIdx.x, ty = threadIdx.y;   // 32 x 8
    if (b < 4096) {
        int kb = (b >> 7) * 32, nb = (b & 127) * 32;
#pragma unroll
        for (int i = 0; i < 4; i++)
            t[ty + i * 8][tx] = __uint_as_float(
                f2tf(__ldg(Wpc + (size_t)(kb + ty + i * 8) * 4096 + nb + tx)));
        __syncthreads();
#pragma unroll
        for (int i = 0; i < 4; i++)
            g_wpcT[(size_t)(nb + ty + i * 8) * 1024 + kb + tx] = t[tx][ty + i * 8];
    } else if (b < 4352) {
        int bb = b - 4096;
        int kb = (bb >> 3) * 32, nb = (bb & 7) * 32;
#pragma unroll
        for (int i = 0; i < 4; i++) {
            int n = nb + tx;
            t[ty + i * 8][tx] = (n < NRELC)
                ? __uint_as_float(f2tf(__ldg(Wctx + (size_t)(kb + ty + i * 8) * NRELC + n)))
                : 0.f;
        }
        __syncthreads();
#pragma unroll
        for (int i = 0; i < 4; i++)
            g_wctxT[(size_t)(nb + ty + i * 8) * 1024 + kb + tx] = t[tx][ty + i * 8];
    } else {
        // Wrel padded [4096][64]
        int idx = (b - 4352) * 256 + ty * 32 + tx;   // < 262144
        int n = idx >> 6, c = idx & 63;
        g_wrelp[idx] = (c < NRELC)
            ? __uint_as_float(f2tf(__ldg(Wrel + (size_t)n * NRELC + c)))
            : 0.f;
    }
}

// ===========================================================================
// Kernel init: out = b_rel + b_ctx + freq[pair_pred] + Hc[p0] + Tc[p1]
// ===========================================================================
__global__ void k_init(const int* __restrict__ pair_idx, const int* __restrict__ obj_preds,
                       const float* __restrict__ brel, const float* __restrict__ bctx,
                       const float* __restrict__ freq, float* __restrict__ out) {
    int idx = blockIdx.x * 256 + threadIdx.x;
    if (idx >= NREL * NRELC) return;
    int i = idx / NRELC;
    int c = idx - i * NRELC;
    int p0 = __ldg(pair_idx + 2 * i);
    int p1 = __ldg(pair_idx + 2 * i + 1);
    int pp = __ldg(obj_preds + p0) * NOBJC + __ldg(obj_preds + p1);
    out[idx] = __ldg(brel + c) + __ldg(bctx + c) + __ldg(freq + (size_t)pp * NRELC + c)
             + __ldg(g_Hc + (size_t)p0 * 128 + c) + __ldg(g_Tc + (size_t)p1 * 128 + c);
}

// ===========================================================================
// Kernel 1: edge_rep = tf32round(edge_ctx @ W_post_emb + b)  (legacy tf32 mma)
// ===========================================================================
__device__ __forceinline__ void stA1(unsigned* __restrict__ Ab, const float4 (&ra)[4], int tid) {
#pragma unroll
    for (int i = 0; i < 4; i++) {
        int s = tid + i * 256, r = s >> 3, kq = s & 7;
        unsigned* p = Ab + r * ASTR + kq * 4;
        p[0] = f2tf(ra[i].x); p[1] = f2tf(ra[i].y); p[2] = f2tf(ra[i].z); p[3] = f2tf(ra[i].w);
    }
}
__device__ __forceinline__ void stB1(unsigned* __restrict__ Bb, const float4 (&rb)[4], int tid) {
#pragma unroll
    for (int i = 0; i < 4; i++) {
        int s = tid + i * 256, kk = s >> 5, cq = s & 31;
        unsigned* p = Bb + kk * BSTR + cq * 4;
        p[0] = f2tf(rb[i].x); p[1] = f2tf(rb[i].y); p[2] = f2tf(rb[i].z); p[3] = f2tf(rb[i].w);
    }
}
__device__ __forceinline__ void mma_tile1(float (&acc)[4][4][4], const unsigned* __restrict__ Ab,
                                          const unsigned* __restrict__ Bb, int wr, int wc, int lane) {
#pragma unroll
    for (int ks = 0; ks < 4; ks++) {
        unsigned af[4][4], bf[4][2];
#pragma unroll
        for (int tm = 0; tm < 4; tm++) {
            const unsigned* p = Ab + (wr * 64 + tm * 16 + (lane >> 2)) * ASTR + ks * 8 + (lane & 3);
            af[tm][0] = p[0]; af[tm][1] = p[8 * ASTR]; af[tm][2] = p[4]; af[tm][3] = p[8 * ASTR + 4];
        }
#pragma unroll
        for (int tn = 0; tn < 4; tn++) {
            const unsigned* p = Bb + (ks * 8 + (lane & 3)) * BSTR + wc * 32 + tn * 8 + (lane >> 2);
            bf[tn][0] = p[0]; bf[tn][1] = p[4 * BSTR];
        }
#pragma unroll
        for (int tm = 0; tm < 4; tm++)
#pragma unroll
            for (int tn = 0; tn < 4; tn++) mma8(acc[tm][tn], af[tm], bf[tn]);
    }
}

__global__ void __launch_bounds__(256, 1) k1_edge_rep(
    const float* __restrict__ A, const float* __restrict__ B, const float* __restrict__ bias) {
    extern __shared__ unsigned sm1[];
    unsigned* As = sm1;
    unsigned* Bs = sm1 + 2 * 128 * ASTR;
    const int tid = threadIdx.x, lane = tid & 31, wid = tid >> 5;
    const int wr = wid >> 2, wc = wid & 3;
    const int m0 = blockIdx.x * 128, n0 = blockIdx.y * 128;

    float acc[4][4][4];
#pragma unroll
    for (int a = 0; a < 4; a++)
#pragma unroll
        for (int b = 0; b < 4; b++)
#pragma unroll
            for (int c = 0; c < 4; c++) acc[a][b][c] = 0.f;

    float4 ra[4], rb[4];
#pragma unroll
    for (int i = 0; i < 4; i++) {
        int s = tid + i * 256;
        { int r = s >> 3, kq = s & 7;
          ra[i] = __ldg((const float4*)(A + (size_t)(m0 + r) * HID + kq * 4)); }
        { int kk = s >> 5, cq = s & 31;
          rb[i] = __ldg((const float4*)(B + (size_t)kk * 1024 + n0 + cq * 4)); }
    }
    stA1(As, ra, tid); stB1(Bs, rb, tid);
    __syncthreads();

    int buf = 0;
    for (int kt = 0; kt < 16; kt++) {
        if (kt < 15) {
            int k0 = (kt + 1) * 32;
#pragma unroll
            for (int i = 0; i < 4; i++) {
                int s = tid + i * 256;
                { int r = s >> 3, kq = s & 7;
                  ra[i] = __ldg((const float4*)(A + (size_t)(m0 + r) * HID + k0 + kq * 4)); }
                { int kk = s >> 5, cq = s & 31;
                  rb[i] = __ldg((const float4*)(B + (size_t)(k0 + kk) * 1024 + n0 + cq * 4)); }
            }
        }
        mma_tile1(acc, As + buf * 128 * ASTR, Bs + buf * 32 * BSTR, wr, wc, lane);
        if (kt < 15) { stA1(As + (buf ^ 1) * 128 * ASTR, ra, tid); stB1(Bs + (buf ^ 1) * 32 * BSTR, rb, tid); }
        __syncthreads();
        buf ^= 1;
    }

#pragma unroll
    for (int tm = 0; tm < 4; tm++) {
        int r = m0 + wr * 64 + tm * 16 + (lane >> 2);
#pragma unroll
        for (int tn = 0; tn < 4; tn++) {
            int c = n0 + wc * 32 + tn * 8 + 2 * (lane & 3);
            float2 bb = *(const float2*)(bias + c);
            float2 v0, v1;
            v0.x = __uint_as_float(f2tf(acc[tm][tn][0] + bb.x));
            v0.y = __uint_as_float(f2tf(acc[tm][tn][1] + bb.y));
            v1.x = __uint_as_float(f2tf(acc[tm][tn][2] + bb.x));
            v1.y = __uint_as_float(f2tf(acc[tm][tn][3] + bb.y));
            *(float2*)(g_edge_rep + (size_t)r * 1024 + c) = v0;
            *(float2*)(g_edge_rep + (size_t)(r + 8) * 1024 + c) = v1;
        }
    }
}

// ===========================================================================
// Kernel H: H = head@Wpc_top, T = tail@Wpc_bot, Hc/Tc = head/tail @ Wctx.
// R16 mainloop (128 thr, warp 64x64, 3-stage cp.async, ldsm), no gather.
// blockIdx: half(2) x ntile(33) x mtile(64) = 4224 CTAs.
// ===========================================================================
__global__ void __launch_bounds__(128) kH() {
    extern __shared__ char smem[];
    const uint32_t sbu = s2u(smem);
    const int tid = threadIdx.x, lane = tid & 31, wid = tid >> 5;
    const int wr = wid >> 1, wc = wid & 1;       // 2 x 2 warp grid
    const int bx = blockIdx.x;
    const int half = bx / 2112;                  // 33*64
    const int rem = bx - half * 2112;
    const int ntile = rem >> 6;
    const int m0 = (rem & 63) * 128;
    const int kbase = half * 512;
    const bool real = (ntile < 32);
    const float* gBT = real ? g_wpcT : g_wctxT;  // [n][1024 k]
    const int nb = real ? ntile * 128 : 0;
    const float* er = g_edge_rep;

    const int a_lrow = (lane & 7) + ((lane >> 3) & 1) * 8;
    const int a_lcol = (lane >> 4) * 4;
    const int b_lrow = (lane & 7) + ((lane >> 4) & 1) * 8;
    const int b_lcol = ((lane >> 3) & 1) * 4;

    const int skq4 = (tid & 7) * 4;
    const int r0i = tid >> 3;
    const uint32_t abase0 = (uint32_t)(r0i * ASTR + skq4) * 4;
    const uint32_t bbase0 = (uint32_t)(r0i * BSTR2 + skq4) * 4;

    float acc[4][8][4];
#pragma unroll
    for (int a = 0; a < 4; a++)
#pragma unroll
        for (int b = 0; b < 8; b++)
#pragma unroll
            for (int c = 0; c < 4; c++) acc[a][b][c] = 0.f;

    // prologue: stages 0,1
#pragma unroll
    for (int p = 0; p < 2; p++) {
        const int k0 = p * 32;
        uint32_t ab = sbu + p * STG + abase0;
        uint32_t bb = sbu + p * STG + ABUF + bbase0;
#pragma unroll
        for (int i = 0; i < 8; i++)
            cp16(ab + i * (16 * ASTR * 4), er + (size_t)(m0 + r0i + i * 16) * 1024 + kbase + k0 + skq4);
#pragma unroll
        for (int i = 0; i < 8; i++)
            cp16(bb + i * (16 * BSTR2 * 4), gBT + (size_t)(nb + r0i + i * 16) * 1024 + kbase + k0 + skq4);
        cp_commit();
    }

    // main loop: 16 chunks of BK=32 (K = 512)
    for (int kc = 0; kc < 16; kc++) {
        cp_wait1();
        __syncthreads();
        if (kc < 14) {
            const int k0 = (kc + 2) * 32;
            const int st = (kc + 2) % 3;
            uint32_t ab = sbu + st * STG + abase0;
            uint32_t bb = sbu + st * STG + ABUF + bbase0;
#pragma unroll
            for (int i = 0; i < 8; i++)
                cp16(ab + i * (16 * ASTR * 4), er + (size_t)(m0 + r0i + i * 16) * 1024 + kbase + k0 + skq4);
#pragma unroll
            for (int i = 0; i < 8; i++)
                cp16(bb + i * (16 * BSTR2 * 4), gBT + (size_t)(nb + r0i + i * 16) * 1024 + kbase + k0 + skq4);
        }
        cp_commit();

        const int st = kc % 3;
        const uint32_t Ab = sbu + st * STG;
        const uint32_t Bb = sbu + st * STG + ABUF;
#pragma unroll
        for (int ks = 0; ks < 4; ks++) {
            unsigned af[4][4], bf[4][4];
#pragma unroll
            for (int tm = 0; tm < 4; tm++)
                ldsm4(af[tm], Ab + (uint32_t)(((wr * 64 + tm * 16 + a_lrow) * ASTR
                                               + ks * 8 + a_lcol) * 4));
#pragma unroll
            for (int tb = 0; tb < 4; tb++)
                ldsm4(bf[tb], Bb + (uint32_t)(((wc * 64 + tb * 16 + b_lrow) * BSTR2
                                               + ks * 8 + b_lcol) * 4));
#pragma unroll
            for (int tm = 0; tm < 4; tm++)
#pragma unroll
                for (int tn = 0; tn < 8; tn++)
                    mma8s(acc[tm][tn], af[tm],
                          bf[tn >> 1][(tn & 1) * 2], bf[tn >> 1][(tn & 1) * 2 + 1]);
        }
    }

    // store fp32 results
#pragma unroll
    for (int tm = 0; tm < 4; tm++) {
        int m = m0 + wr * 64 + tm * 16 + (lane >> 2);
#pragma unroll
        for (int tn = 0; tn < 8; tn++) {
            int col = wc * 64 + tn * 8 + 2 * (lane & 3);
            float2 v0 = make_float2(acc[tm][tn][0], acc[tm][tn][1]);
            float2 v1 = make_float2(acc[tm][tn][2], acc[tm][tn][3]);
            if (real) {
                float* dst = (half ? g_T : g_H) + (size_t)m * 4096 + ntile * 128 + col;
                *(float2*)dst = v0;
                *(float2*)(dst + (size_t)8 * 4096) = v1;
            } else {
                float* dst = (half ? g_Tc : g_Hc) + (size_t)m * 128 + col;
                *(float2*)dst = v0;
                *(float2*)(dst + 8 * 128) = v1;
            }
        }
    }
}

// ===========================================================================
// Kernel 2b: per CTA = (m-tile of 128 relations, half of 64 n-chunks).
// Per chunk (64 cols): V = f2tf((H[p0]+T[p1]+bpc)*U) -> smem (double-buffered),
// acc2 += V @ Wrel_chunk (cp.async-prefetched). atomicAdd into init'd out.
// 256 threads, 8 warps as 4x2, warp tile 32x32. 2 CTAs/SM.
// ===========================================================================
__global__ void __launch_bounds__(256, 2) k2b(
    const int* __restrict__ pair_idx,
    const float* __restrict__ U,
    const float* __restrict__ bpc,
    float* __restrict__ out) {
    extern __shared__ char smem[];
    const uint32_t sbu = s2u(smem);
    const int tid = threadIdx.x, lane = tid & 31, wid = tid >> 5;
    const int wr2 = wid >> 1, wc2 = wid & 1;     // 4 x 2 warp grid
    const int m0 = (blockIdx.x >> 1) * 128;
    const int kc0 = (blockIdx.x & 1) * 32;

    int* rows0 = (int*)(smem + OFFI2);
    int* rows1 = rows0 + 128;
    if (tid < 128) {
        rows0[tid] = pair_idx[2 * (m0 + tid)];
        rows1[tid] = pair_idx[2 * (m0 + tid) + 1];
    }
    __syncthreads();

    const int r = tid >> 1, h = tid & 1;
    const float* Hrow = g_H + (size_t)rows0[r] * 4096;
    const float* Trow = g_T + (size_t)rows1[r] * 4096;
    const float* Urow = U + (size_t)(m0 + r) * 4096;

    const int a_lrow = (lane & 7) + ((lane >> 3) & 1) * 8;
    const int a_lcol = (lane >> 4) * 4;

    float acc2[2][4][4];
#pragma unroll
    for (int a = 0; a < 2; a++)
#pragma unroll
        for (int b = 0; b < 4; b++)
#pragma unroll
            for (int c = 0; c < 4; c++) acc2[a][b][c] = 0.f;

    // Ws prologue: chunk kc0 into buf 0
    {
        const int n0 = kc0 * 64;
#pragma unroll
        for (int i = 0; i < 4; i++) {
            int s = tid + i * 256, kn = s >> 4, cq = s & 15;
            cp16(sbu + OFFW2 + (uint32_t)(kn * 288 + cq * 16),
                 g_wrelp + (size_t)(n0 + kn) * 64 + cq * 4);
        }
        cp_commit();
    }

    for (int j = 0; j < 32; j++) {
        const int kc = kc0 + j;
        const int n0 = kc * 64;
        const int buf = j & 1;

        // ---- build V chunk into Vs[buf] (interleaved 16B so lane-pairs
        //      cover 32B sectors; thread covers 32 of the 64 cols of row r) ----
        char* vb = smem + buf * VBUF + (size_t)r * (V2STR * 4);
#pragma unroll
        for (int q = 0; q < 8; q++) {
            int c = n0 + (2 * q + h) * 4;
            float4 hv = __ldg((const float4*)(Hrow + c));
            float4 tv = __ldg((const float4*)(Trow + c));
            float4 uv = __ldg((const float4*)(Urow + c));
            float4 bb = __ldg((const float4*)(bpc + c));
            uint4 o;
            o.x = f2tf((hv.x + tv.x + bb.x) * uv.x);
            o.y = f2tf((hv.y + tv.y + bb.y) * uv.y);
            o.z = f2tf((hv.z + tv.z + bb.z) * uv.z);
            o.w = f2tf((hv.w + tv.w + bb.w) * uv.w);
            *(uint4*)(vb + (2 * q + h) * 16) = o;
        }

        cp_wait0();          // Ws[buf] (issued last iter) arrived
        __syncthreads();     // V visible; all warps done with MMA(j-1)

        // ---- prefetch Ws for next chunk into buf^1 (overlaps this MMA) ----
        if (j < 31) {
            const int n1 = (kc + 1) * 64;
#pragma unroll
            for (int i = 0; i < 4; i++) {
                int s = tid + i * 256, kn = s >> 4, cq = s & 15;
                cp16(sbu + OFFW2 + (uint32_t)((buf ^ 1) * WBUF2 + kn * 288 + cq * 16),
                     g_wrelp + (size_t)(n1 + kn) * 64 + cq * 4);
            }
            cp_commit();
        }

        // ---- acc2 += V(128x64) @ Ws(64x64) ----
        const uint32_t Vb = sbu + buf * VBUF;
        const unsigned* Wsp = (const unsigned*)(smem + OFFW2 + buf * WBUF2);
#pragma unroll
        for (int ks = 0; ks < 8; ks++) {
            unsigned af[2][4], bf[4][2];
#pragma unroll
            for (int tm = 0; tm < 2; tm++)
                ldsm4(af[tm], Vb + (uint32_t)(((wr2 * 32 + tm * 16 + a_lrow) * V2STR
                                               + ks * 8 + a_lcol) * 4));
#pragma unroll
            for (int tn = 0; tn < 4; tn++) {
                const unsigned* p = Wsp + (ks * 8 + (lane & 3)) * W2STR + wc2 * 32 + tn * 8 + (lane >> 2);
                bf[tn][0] = p[0]; bf[tn][1] = p[4 * W2STR];
            }
#pragma unroll
            for (int tm = 0; tm < 2; tm++)
#pragma unroll
                for (int tn = 0; tn < 4; tn++)
                    mma8(acc2[tm][tn], af[tm], bf[tn]);
        }
    }

    // ---- combine partials into pre-initialized out ----
#pragma unroll
    for (int tm = 0; tm < 2; tm++) {
        int rl = wr2 * 32 + tm * 16 + (lane >> 2);
#pragma unroll
        for (int tn = 0; tn < 4; tn++) {
            int c = wc2 * 32 + tn * 8 + 2 * (lane & 3);
#pragma unroll
            for (int q = 0; q < 4; q++) {
                int row = rl + ((q >= 2) ? 8 : 0);
                int col = c + (q & 1);
                if (col < NRELC)
                    atomicAdd(out + (size_t)(m0 + row) * NRELC + col, acc2[tm][tn][q]);
            }
        }
    }
}

// ===========================================================================
// Launch
// ===========================================================================
extern "C" void kernel_launch(void* const* d_in, const int* in_sizes, int n_in,
                              void* d_out, int out_size) {
    (void)in_sizes; (void)n_in; (void)out_size;
    const float* edge_ctx  = (const float*)d_in[0];
    const int*   obj_preds = (const int*)d_in[1];
    const int*   pair_idx  = (const int*)d_in[2];
    const float* U         = (const float*)d_in[3];
    const float* Wpe       = (const float*)d_in[4];
    const float* bpe       = (const float*)d_in[5];
    const float* Wpc       = (const float*)d_in[6];
    const float* bpc       = (const float*)d_in[7];
    const float* Wrel      = (const float*)d_in[8];
    const float* brel      = (const float*)d_in[9];
    const float* Wctx      = (const float*)d_in[10];
    const float* bctx      = (const float*)d_in[11];
    const float* freq      = (const float*)d_in[12];
    float* out = (float*)d_out;

    cudaFuncSetAttribute(k1_edge_rep, cudaFuncAttributeMaxDynamicSharedMemorySize, K1_SMEM);
    cudaFuncSetAttribute(kH,          cudaFuncAttributeMaxDynamicSharedMemorySize, KH_SMEM);
    cudaFuncSetAttribute(k2b,         cudaFuncAttributeMaxDynamicSharedMemorySize, K2BS);

    k0_prep_t<<<4352 + 1024, dim3(32, 8)>>>(Wpc, Wctx, Wrel);
    k1_edge_rep<<<dim3(64, 8), 256, K1_SMEM>>>(edge_ctx, Wpe, bpe);
    kH<<<4224, 128, KH_SMEM>>>();
    k_init<<<(NREL * NRELC + 255) / 256, 256>>>(pair_idx, obj_preds, brel, bctx, freq, out);
    k2b<<<1024, 256, K2BS>>>(pair_idx, U, bpc, out);
}